// round 5
// baseline (speedup 1.0000x reference)
#include <cuda_runtime.h>
#include <cuda_bf16.h>
#include <math.h>

// Problem dims (fixed by the reference)
#define T_STEPS 512
#define BATCH   256
#define DIM     1024
#define HID     1024
#define OUTD    5

// Persistent recurrence geometry: 128 CTAs = 8 m-tiles(32) x 16 n-tiles(64)
#define GRID_P  128
#define MT      32
#define NT      64

// Scratch
__device__ float          g_E[(size_t)T_STEPS * BATCH * HID];     // fp32 input proj
__device__ __nv_bfloat16  g_hbf[2][(size_t)BATCH * HID];          // bf16 h transport
__device__ float          g_hfinal[(size_t)BATCH * HID];          // fp32 final h
__device__ unsigned       g_grp[8][32];                           // per-m-group barrier ctrs

// ---------------------------------------------------------------------------
// bf16 mma.sync helper (m16n8k16, fp32 accumulate)
// ---------------------------------------------------------------------------
__device__ __forceinline__ void mma_bf16(float d[4],
                                         unsigned a0, unsigned a1,
                                         unsigned a2, unsigned a3,
                                         unsigned b0, unsigned b1)
{
    asm volatile(
        "mma.sync.aligned.m16n8k16.row.col.f32.bf16.bf16.f32 "
        "{%0,%1,%2,%3}, {%4,%5,%6,%7}, {%8,%9}, {%0,%1,%2,%3};"
        : "+f"(d[0]), "+f"(d[1]), "+f"(d[2]), "+f"(d[3])
        : "r"(a0), "r"(a1), "r"(a2), "r"(a3), "r"(b0), "r"(b1));
}

__device__ __forceinline__ float sigmoidf_fast(float x)
{
    return 1.0f / (1.0f + __expf(-x));
}

// split a float pair into bf16 hi + bf16 lo (residual) packed words
__device__ __forceinline__ void split2(float a, float b, unsigned& hi, unsigned& lo)
{
    __nv_bfloat162 h = __float22bfloat162_rn(make_float2(a, b));
    float ra = a - __low2float(h);
    float rb = b - __high2float(h);
    __nv_bfloat162 l = __float22bfloat162_rn(make_float2(ra, rb));
    hi = *(unsigned*)&h;
    lo = *(unsigned*)&l;
}

// ---------------------------------------------------------------------------
// E = x @ W_in^T + b_in via error-compensated bf16 tensor-core GEMM.
// (unchanged from R3 — validated)
// ---------------------------------------------------------------------------
__global__ void __launch_bounds__(256, 2)
egemm_bf16x3(const float* __restrict__ X,
             const float* __restrict__ Wg,
             const float* __restrict__ bias,
             float* __restrict__ E)
{
    extern __shared__ unsigned es[];
    unsigned* Ahi = es;
    unsigned* Alo = es + 8192;
    unsigned* Bhi = es + 16384;
    unsigned* Blo = es + 20480;

    const int tid  = threadIdx.x;
    const int lane = tid & 31;
    const int w    = tid >> 5;
    const int qid  = lane >> 2;
    const int c    = lane & 3;
    const int g    = w >> 1;
    const int subm = (w & 1) * 16;

    const int n0 = blockIdx.x * 64;
    const int m0 = blockIdx.y * 128;

    const int srow = tid >> 3;
    const int ssl  = tid & 7;
    const int sx   = ssl & 3;

    float acc[4][2][4];
    #pragma unroll
    for (int a = 0; a < 4; a++)
        #pragma unroll
        for (int b = 0; b < 2; b++)
            #pragma unroll
            for (int d = 0; d < 4; d++) acc[a][b][d] = 0.0f;

    for (int ch = 0; ch < 8; ch++) {
        __syncthreads();
        const float* xbase = X + (size_t)(m0 + srow) * 1024 + ch * 128 + ssl * 16;
        #pragma unroll
        for (int jj = 0; jj < 4; jj++) {
            const float4* p = (const float4*)(xbase + (size_t)jj * 32 * 1024);
            float4 f0 = p[0], f1 = p[1], f2 = p[2], f3 = p[3];
            unsigned h[8], l[8];
            split2(f0.x, f0.y, h[0], l[0]); split2(f0.z, f0.w, h[1], l[1]);
            split2(f1.x, f1.y, h[2], l[2]); split2(f1.z, f1.w, h[3], l[3]);
            split2(f2.x, f2.y, h[4], l[4]); split2(f2.z, f2.w, h[5], l[5]);
            split2(f3.x, f3.y, h[6], l[6]); split2(f3.z, f3.w, h[7], l[7]);
            uint2* dh = (uint2*)&Ahi[jj * 2048 + ssl * 256 + srow * 8];
            uint2* dl = (uint2*)&Alo[jj * 2048 + ssl * 256 + srow * 8];
            dh[0 ^ sx] = make_uint2(h[0], h[4]); dh[1 ^ sx] = make_uint2(h[1], h[5]);
            dh[2 ^ sx] = make_uint2(h[2], h[6]); dh[3 ^ sx] = make_uint2(h[3], h[7]);
            dl[0 ^ sx] = make_uint2(l[0], l[4]); dl[1 ^ sx] = make_uint2(l[1], l[5]);
            dl[2 ^ sx] = make_uint2(l[2], l[6]); dl[3 ^ sx] = make_uint2(l[3], l[7]);
        }
        #pragma unroll
        for (int jj = 0; jj < 2; jj++) {
            int nrow = srow + jj * 32;
            const float4* p = (const float4*)(Wg + (size_t)(n0 + nrow) * 1024
                                              + ch * 128 + ssl * 16);
            float4 f0 = p[0], f1 = p[1], f2 = p[2], f3 = p[3];
            unsigned h[8], l[8];
            split2(f0.x, f0.y, h[0], l[0]); split2(f0.z, f0.w, h[1], l[1]);
            split2(f1.x, f1.y, h[2], l[2]); split2(f1.z, f1.w, h[3], l[3]);
            split2(f2.x, f2.y, h[4], l[4]); split2(f2.z, f2.w, h[5], l[5]);
            split2(f3.x, f3.y, h[6], l[6]); split2(f3.z, f3.w, h[7], l[7]);
            uint2* dh = (uint2*)&Bhi[ssl * 512 + nrow * 8];
            uint2* dl = (uint2*)&Blo[ssl * 512 + nrow * 8];
            dh[0 ^ sx] = make_uint2(h[0], h[4]); dh[1 ^ sx] = make_uint2(h[1], h[5]);
            dh[2 ^ sx] = make_uint2(h[2], h[6]); dh[3 ^ sx] = make_uint2(h[3], h[7]);
            dl[0 ^ sx] = make_uint2(l[0], l[4]); dl[1 ^ sx] = make_uint2(l[1], l[5]);
            dl[2 ^ sx] = make_uint2(l[2], l[6]); dl[3 ^ sx] = make_uint2(l[3], l[7]);
        }
        __syncthreads();

        #pragma unroll
        for (int sl = 0; sl < 8; sl++) {
            int axw = g * 2048 + sl * 256 + (subm + qid) * 8 + 2 * (c ^ (sl & 3));
            uint2 ah0 = *(const uint2*)&Ahi[axw];
            uint2 ah1 = *(const uint2*)&Ahi[axw + 64];
            uint2 al0 = *(const uint2*)&Alo[axw];
            uint2 al1 = *(const uint2*)&Alo[axw + 64];
            #pragma unroll
            for (int ng = 0; ng < 4; ng++) {
                int bxw = sl * 512 + ng * 128 + qid * 8 + 2 * (c ^ (sl & 3));
                uint2 bh0 = *(const uint2*)&Bhi[bxw];
                uint2 bh1 = *(const uint2*)&Bhi[bxw + 64];
                uint2 bl0 = *(const uint2*)&Blo[bxw];
                uint2 bl1 = *(const uint2*)&Blo[bxw + 64];
                mma_bf16(acc[ng][0], ah0.x, ah1.x, ah0.y, ah1.y, bh0.x, bh0.y);
                mma_bf16(acc[ng][0], ah0.x, ah1.x, ah0.y, ah1.y, bl0.x, bl0.y);
                mma_bf16(acc[ng][0], al0.x, al1.x, al0.y, al1.y, bh0.x, bh0.y);
                mma_bf16(acc[ng][1], ah0.x, ah1.x, ah0.y, ah1.y, bh1.x, bh1.y);
                mma_bf16(acc[ng][1], ah0.x, ah1.x, ah0.y, ah1.y, bl1.x, bl1.y);
                mma_bf16(acc[ng][1], al0.x, al1.x, al0.y, al1.y, bh1.x, bh1.y);
            }
        }
    }

    const int mrow = m0 + w * 16 + qid;
    #pragma unroll
    for (int ng = 0; ng < 4; ng++) {
        #pragma unroll
        for (int hh = 0; hh < 2; hh++) {
            int col = n0 + ng * 16 + hh * 8 + 2 * c;
            float2 b2 = *(const float2*)(bias + col);
            float2 o0, o1;
            o0.x = acc[ng][hh][0] + b2.x; o0.y = acc[ng][hh][1] + b2.y;
            o1.x = acc[ng][hh][2] + b2.x; o1.y = acc[ng][hh][3] + b2.y;
            *(float2*)&E[(size_t)mrow * 1024 + col]       = o0;
            *(float2*)&E[(size_t)(mrow + 8) * 1024 + col] = o1;
        }
    }
}

// ---------------------------------------------------------------------------
// h0 -> bf16 transport buffer (read at t=0 as g_hbf[1])
// ---------------------------------------------------------------------------
__global__ void h0_to_bf16(const float* __restrict__ h0)
{
    int i = blockIdx.x * 256 + threadIdx.x;
    g_hbf[1][i] = __float2bfloat16(h0[i]);
}

// ---------------------------------------------------------------------------
// Per-m-group barrier: 16 CTAs, release/acquire atomics, monotonic counter.
// ---------------------------------------------------------------------------
__device__ __forceinline__ void group_barrier(int grp, unsigned target)
{
    __syncthreads();
    if (threadIdx.x == 0) {
        unsigned* ctr = &g_grp[grp][0];
        asm volatile("red.release.gpu.global.add.u32 [%0], %1;"
                     :: "l"(ctr), "r"(1u) : "memory");
        unsigned v;
        do {
            asm volatile("ld.acquire.gpu.global.u32 %0, [%1];"
                         : "=r"(v) : "l"(ctr) : "memory");
        } while (v < target);
    }
    __syncthreads();
}

// ---------------------------------------------------------------------------
// Persistent recurrence with bf16 tensor-core mma.
// R4 change: per step, bulk-load the WHOLE 32x1024 h tile (16 front-batched
// LDG.128/thread, MLP=16), stage into a single 64KB smem buffer, ONE
// __syncthreads, then all 64 mma slices run back-to-back with no memory deps.
// Removes 7 syncthreads + per-chunk L2-latency exposure from the step path.
// ---------------------------------------------------------------------------
__global__ void __launch_bounds__(256, 1)
rnn_persistent(const float* __restrict__ W_h,
               const float* __restrict__ b_h)
{
    extern __shared__ unsigned smw[];
    unsigned* Ws = smw;              // 32768 words (128KB)
    unsigned* As = smw + 32768;      // 16384 words (64KB) — full h tile

    const int tid  = threadIdx.x;
    const int lane = tid & 31;
    const int w    = tid >> 5;
    const int qid  = lane >> 2;
    const int c    = lane & 3;
    const int mw   = (w >> 2) * 16;
    const int nw   = (w & 3) * 16;
    const int cta  = blockIdx.x;
    const int grp  = cta >> 4;
    const int m0   = grp * MT;
    const int n0   = (cta & 15) * NT;

    // ---- fill Ws (once): fp32 -> bf16x2, fragment-shuffled ----
    for (int i = tid; i < NT * 512; i += 256) {
        int n  = i >> 9;
        int kp = i & 511;
        int k  = kp * 2;
        int s  = k >> 4;
        int p  = (k & 15) >> 1;
        float2 wv = *(const float2*)(W_h + (size_t)(n0 + n) * HID + k);
        __nv_bfloat162 bb = __float22bfloat162_rn(wv);
        Ws[s * 512 + n * 8 + (p & 3) * 2 + (p >> 2)] = *(unsigned*)&bb;
    }
    const float2 bh0 = *(const float2*)(b_h + n0 + nw + 2 * c);
    const float2 bh1 = *(const float2*)(b_h + n0 + nw + 8 + 2 * c);
    __syncthreads();

    const int srow = tid >> 3;
    const int ssl  = tid & 7;
    const int sx   = ssl & 3;

    for (int t = 0; t < T_STEPS; t++) {
        const __nv_bfloat16* hin  = g_hbf[(t + 1) & 1];
        __nv_bfloat16*       hout = g_hbf[t & 1];

        // ---- bulk load: whole h tile, 16 int4 per thread, front-batched ----
        const __nv_bfloat16* gsrc = hin + (size_t)(m0 + srow) * HID + ssl * 16;
        int4 v[16];
        #pragma unroll
        for (int ch = 0; ch < 8; ch++) {
            v[2 * ch]     = __ldcg((const int4*)(gsrc + ch * 128));
            v[2 * ch + 1] = __ldcg((const int4*)(gsrc + ch * 128 + 8));
        }

        // epilogue operands (overlap with h loads)
        const float* eb = g_E + ((size_t)t * BATCH + m0 + mw + qid) * HID
                              + n0 + nw + 2 * c;
        float2 e00 = __ldg((const float2*)eb);
        float2 e01 = __ldg((const float2*)(eb + 8));
        float2 e10 = __ldg((const float2*)(eb + 8 * HID));
        float2 e11 = __ldg((const float2*)(eb + 8 * HID + 8));

        // ---- stage all 8 chunks, one sync ----
        #pragma unroll
        for (int ch = 0; ch < 8; ch++) {
            uint2* dp = (uint2*)(As + ch * 2048 + ssl * 256 + srow * 8);
            int4 a = v[2 * ch], b = v[2 * ch + 1];
            dp[0 ^ sx] = make_uint2(a.x, b.x);
            dp[1 ^ sx] = make_uint2(a.y, b.y);
            dp[2 ^ sx] = make_uint2(a.z, b.z);
            dp[3 ^ sx] = make_uint2(a.w, b.w);
        }
        __syncthreads();

        float d0[4] = {0.f, 0.f, 0.f, 0.f};
        float d1[4] = {0.f, 0.f, 0.f, 0.f};

        // ---- compute: 64 slices, no memory dependencies ----
        #pragma unroll
        for (int ch = 0; ch < 8; ch++) {
            const unsigned* Ab = As + ch * 2048;
            #pragma unroll
            for (int sl = 0; sl < 8; sl++) {
                int aoff = sl * 256 + (mw + qid) * 8 + 2 * (c ^ (sl & 3));
                uint2 aLo = *(const uint2*)(Ab + aoff);
                uint2 aHi = *(const uint2*)(Ab + aoff + 64);
                const unsigned* Wb = Ws + (ch * 8 + sl) * 512 + (nw + qid) * 8 + 2 * c;
                uint2 b0 = *(const uint2*)(Wb);
                uint2 b1 = *(const uint2*)(Wb + 64);
                mma_bf16(d0, aLo.x, aHi.x, aLo.y, aHi.y, b0.x, b0.y);
                mma_bf16(d1, aLo.x, aHi.x, aLo.y, aHi.y, b1.x, b1.y);
            }
        }

        // ---- epilogue: z = d + b_h + E; h = sigmoid(z) (all fp32) ----
        float s00x = sigmoidf_fast(d0[0] + bh0.x + e00.x);
        float s00y = sigmoidf_fast(d0[1] + bh0.y + e00.y);
        float s10x = sigmoidf_fast(d0[2] + bh0.x + e10.x);
        float s10y = sigmoidf_fast(d0[3] + bh0.y + e10.y);
        float s01x = sigmoidf_fast(d1[0] + bh1.x + e01.x);
        float s01y = sigmoidf_fast(d1[1] + bh1.y + e01.y);
        float s11x = sigmoidf_fast(d1[2] + bh1.x + e11.x);
        float s11y = sigmoidf_fast(d1[3] + bh1.y + e11.y);

        __nv_bfloat16* ho = hout + (size_t)(m0 + mw + qid) * HID + n0 + nw + 2 * c;
        *(__nv_bfloat162*)(ho)               = __float22bfloat162_rn(make_float2(s00x, s00y));
        *(__nv_bfloat162*)(ho + 8)           = __float22bfloat162_rn(make_float2(s01x, s01y));
        *(__nv_bfloat162*)(ho + 8 * HID)     = __float22bfloat162_rn(make_float2(s10x, s10y));
        *(__nv_bfloat162*)(ho + 8 * HID + 8) = __float22bfloat162_rn(make_float2(s11x, s11y));

        if (t == T_STEPS - 1) {
            float* hf = g_hfinal + (size_t)(m0 + mw + qid) * HID + n0 + nw + 2 * c;
            *(float2*)(hf)               = make_float2(s00x, s00y);
            *(float2*)(hf + 8)           = make_float2(s01x, s01y);
            *(float2*)(hf + 8 * HID)     = make_float2(s10x, s10y);
            *(float2*)(hf + 8 * HID + 8) = make_float2(s11x, s11y);
        } else {
            group_barrier(grp, 16u * (t + 1));
        }
    }
}

// ---------------------------------------------------------------------------
// Final head (R4: all 128 threads participate in the dot product)
// ---------------------------------------------------------------------------
__global__ void finalize_kernel(const float* __restrict__ h,
                                const float* __restrict__ state_in,
                                const float* __restrict__ W_o,
                                const float* __restrict__ b_o,
                                float* __restrict__ out)
{
    const int b    = blockIdx.x;
    const int tid  = threadIdx.x;
    const int lane = tid & 31;
    const int wid  = tid >> 5;

    __shared__ float red[4][OUTD];
    __shared__ float logits[OUTD];

    float acc[OUTD];
    #pragma unroll
    for (int o = 0; o < OUTD; o++) acc[o] = 0.0f;
    for (int k = tid; k < HID; k += 128) {
        float hv = h[(size_t)b * HID + k];
        #pragma unroll
        for (int o = 0; o < OUTD; o++)
            acc[o] += hv * W_o[(size_t)o * HID + k];
    }
    #pragma unroll
    for (int o = 0; o < OUTD; o++) {
        float v = acc[o];
        #pragma unroll
        for (int s = 16; s > 0; s >>= 1)
            v += __shfl_xor_sync(0xffffffff, v, s);
        if (lane == 0) red[wid][o] = v;
    }
    __syncthreads();

    if (tid == 0) {
        #pragma unroll
        for (int o = 0; o < OUTD; o++)
            logits[o] = red[0][o] + red[1][o] + red[2][o] + red[3][o] + b_o[o];
        float m = logits[0];
        #pragma unroll
        for (int o = 1; o < OUTD; o++) m = fmaxf(m, logits[o]);
        float s = 0.0f;
        #pragma unroll
        for (int o = 0; o < OUTD; o++) s += expf(logits[o] - m);
        float lse = m + logf(s);
        #pragma unroll
        for (int o = 0; o < OUTD; o++)
            out[(size_t)b * OUTD + o] = logits[o] - lse;
    }

    float* hid_out = out + (size_t)BATCH * OUTD;
    float* st_out  = hid_out + (size_t)BATCH * HID;
    for (int k = tid; k < HID; k += blockDim.x) {
        hid_out[(size_t)b * HID + k] = h[(size_t)b * HID + k];
        st_out[(size_t)b * HID + k]  = state_in[(size_t)b * HID + k];
    }
}

extern "C" void kernel_launch(void* const* d_in, const int* in_sizes, int n_in,
                              void* d_out, int out_size)
{
    const float* x    = (const float*)d_in[0];
    const float* h0   = (const float*)d_in[1];
    const float* st   = (const float*)d_in[2];
    const float* W_in = (const float*)d_in[3];
    const float* b_in = (const float*)d_in[4];
    const float* W_h  = (const float*)d_in[5];
    const float* b_h  = (const float*)d_in[6];
    const float* W_o  = (const float*)d_in[7];
    const float* b_o  = (const float*)d_in[8];
    float* out = (float*)d_out;

    float* Eptr = nullptr;
    float* hfin = nullptr;
    unsigned* grpptr = nullptr;
    cudaGetSymbolAddress((void**)&Eptr, g_E);
    cudaGetSymbolAddress((void**)&hfin, g_hfinal);
    cudaGetSymbolAddress((void**)&grpptr, g_grp);

    cudaMemsetAsync(grpptr, 0, 8 * 32 * sizeof(unsigned));

    // 0) h0 -> bf16 transport buffer
    h0_to_bf16<<<(BATCH * HID) / 256, 256>>>(h0);

    // 1) E = x @ W_in^T + b_in (bf16 3-term split, fp32 accumulate)
    {
        const int smem_bytes = 24576 * sizeof(unsigned);  // 96KB
        cudaFuncSetAttribute(egemm_bf16x3,
                             cudaFuncAttributeMaxDynamicSharedMemorySize, smem_bytes);
        dim3 grid(HID / 64, (T_STEPS * BATCH) / 128);
        egemm_bf16x3<<<grid, 256, smem_bytes>>>(x, W_in, b_in, Eptr);
    }

    // 2) Persistent recurrence (bf16 tensor cores, bulk-load steps)
    {
        const int smem_bytes = (32768 + 16384) * sizeof(unsigned);  // 192KB
        cudaFuncSetAttribute(rnn_persistent,
                             cudaFuncAttributeMaxDynamicSharedMemorySize, smem_bytes);
        rnn_persistent<<<GRID_P, 256, smem_bytes>>>(W_h, b_h);
    }

    // 3) Head + output tuple
    finalize_kernel<<<BATCH, 128>>>(hfin, st, W_o, b_o, out);
}

// round 6
// speedup vs baseline: 1.0005x; 1.0005x over previous
#include <cuda_runtime.h>
#include <cuda_bf16.h>
#include <math.h>

// Problem dims (fixed by the reference)
#define T_STEPS 512
#define BATCH   256
#define DIM     1024
#define HID     1024
#define OUTD    5

// Persistent recurrence geometry: 128 CTAs = 8 m-tiles(32) x 16 n-tiles(64)
#define GRID_P  128
#define MT      32
#define NT      64

// Scratch
__device__ float          g_E[(size_t)T_STEPS * BATCH * HID];     // fp32 input proj
__device__ __nv_bfloat16  g_hbf[2][(size_t)BATCH * HID];          // bf16 h transport
__device__ float          g_hfinal[(size_t)BATCH * HID];          // fp32 final h
__device__ unsigned       g_grp[8][32];                           // per-m-group barrier ctrs

// ---------------------------------------------------------------------------
// bf16 mma.sync helper (m16n8k16, fp32 accumulate)
// ---------------------------------------------------------------------------
__device__ __forceinline__ void mma_bf16(float d[4],
                                         unsigned a0, unsigned a1,
                                         unsigned a2, unsigned a3,
                                         unsigned b0, unsigned b1)
{
    asm volatile(
        "mma.sync.aligned.m16n8k16.row.col.f32.bf16.bf16.f32 "
        "{%0,%1,%2,%3}, {%4,%5,%6,%7}, {%8,%9}, {%0,%1,%2,%3};"
        : "+f"(d[0]), "+f"(d[1]), "+f"(d[2]), "+f"(d[3])
        : "r"(a0), "r"(a1), "r"(a2), "r"(a3), "r"(b0), "r"(b1));
}

__device__ __forceinline__ float sigmoidf_fast(float x)
{
    return 1.0f / (1.0f + __expf(-x));
}

// split a float pair into bf16 hi + bf16 lo (residual) packed words
__device__ __forceinline__ void split2(float a, float b, unsigned& hi, unsigned& lo)
{
    __nv_bfloat162 h = __float22bfloat162_rn(make_float2(a, b));
    float ra = a - __low2float(h);
    float rb = b - __high2float(h);
    __nv_bfloat162 l = __float22bfloat162_rn(make_float2(ra, rb));
    hi = *(unsigned*)&h;
    lo = *(unsigned*)&l;
}

// ---------------------------------------------------------------------------
// E = x @ W_in^T + b_in via error-compensated bf16 tensor-core GEMM.
// (unchanged from R3 — validated)
// ---------------------------------------------------------------------------
__global__ void __launch_bounds__(256, 2)
egemm_bf16x3(const float* __restrict__ X,
             const float* __restrict__ Wg,
             const float* __restrict__ bias,
             float* __restrict__ E)
{
    extern __shared__ unsigned es[];
    unsigned* Ahi = es;
    unsigned* Alo = es + 8192;
    unsigned* Bhi = es + 16384;
    unsigned* Blo = es + 20480;

    const int tid  = threadIdx.x;
    const int lane = tid & 31;
    const int w    = tid >> 5;
    const int qid  = lane >> 2;
    const int c    = lane & 3;
    const int g    = w >> 1;
    const int subm = (w & 1) * 16;

    const int n0 = blockIdx.x * 64;
    const int m0 = blockIdx.y * 128;

    const int srow = tid >> 3;
    const int ssl  = tid & 7;
    const int sx   = ssl & 3;

    float acc[4][2][4];
    #pragma unroll
    for (int a = 0; a < 4; a++)
        #pragma unroll
        for (int b = 0; b < 2; b++)
            #pragma unroll
            for (int d = 0; d < 4; d++) acc[a][b][d] = 0.0f;

    for (int ch = 0; ch < 8; ch++) {
        __syncthreads();
        const float* xbase = X + (size_t)(m0 + srow) * 1024 + ch * 128 + ssl * 16;
        #pragma unroll
        for (int jj = 0; jj < 4; jj++) {
            const float4* p = (const float4*)(xbase + (size_t)jj * 32 * 1024);
            float4 f0 = p[0], f1 = p[1], f2 = p[2], f3 = p[3];
            unsigned h[8], l[8];
            split2(f0.x, f0.y, h[0], l[0]); split2(f0.z, f0.w, h[1], l[1]);
            split2(f1.x, f1.y, h[2], l[2]); split2(f1.z, f1.w, h[3], l[3]);
            split2(f2.x, f2.y, h[4], l[4]); split2(f2.z, f2.w, h[5], l[5]);
            split2(f3.x, f3.y, h[6], l[6]); split2(f3.z, f3.w, h[7], l[7]);
            uint2* dh = (uint2*)&Ahi[jj * 2048 + ssl * 256 + srow * 8];
            uint2* dl = (uint2*)&Alo[jj * 2048 + ssl * 256 + srow * 8];
            dh[0 ^ sx] = make_uint2(h[0], h[4]); dh[1 ^ sx] = make_uint2(h[1], h[5]);
            dh[2 ^ sx] = make_uint2(h[2], h[6]); dh[3 ^ sx] = make_uint2(h[3], h[7]);
            dl[0 ^ sx] = make_uint2(l[0], l[4]); dl[1 ^ sx] = make_uint2(l[1], l[5]);
            dl[2 ^ sx] = make_uint2(l[2], l[6]); dl[3 ^ sx] = make_uint2(l[3], l[7]);
        }
        #pragma unroll
        for (int jj = 0; jj < 2; jj++) {
            int nrow = srow + jj * 32;
            const float4* p = (const float4*)(Wg + (size_t)(n0 + nrow) * 1024
                                              + ch * 128 + ssl * 16);
            float4 f0 = p[0], f1 = p[1], f2 = p[2], f3 = p[3];
            unsigned h[8], l[8];
            split2(f0.x, f0.y, h[0], l[0]); split2(f0.z, f0.w, h[1], l[1]);
            split2(f1.x, f1.y, h[2], l[2]); split2(f1.z, f1.w, h[3], l[3]);
            split2(f2.x, f2.y, h[4], l[4]); split2(f2.z, f2.w, h[5], l[5]);
            split2(f3.x, f3.y, h[6], l[6]); split2(f3.z, f3.w, h[7], l[7]);
            uint2* dh = (uint2*)&Bhi[ssl * 512 + nrow * 8];
            uint2* dl = (uint2*)&Blo[ssl * 512 + nrow * 8];
            dh[0 ^ sx] = make_uint2(h[0], h[4]); dh[1 ^ sx] = make_uint2(h[1], h[5]);
            dh[2 ^ sx] = make_uint2(h[2], h[6]); dh[3 ^ sx] = make_uint2(h[3], h[7]);
            dl[0 ^ sx] = make_uint2(l[0], l[4]); dl[1 ^ sx] = make_uint2(l[1], l[5]);
            dl[2 ^ sx] = make_uint2(l[2], l[6]); dl[3 ^ sx] = make_uint2(l[3], l[7]);
        }
        __syncthreads();

        #pragma unroll
        for (int sl = 0; sl < 8; sl++) {
            int axw = g * 2048 + sl * 256 + (subm + qid) * 8 + 2 * (c ^ (sl & 3));
            uint2 ah0 = *(const uint2*)&Ahi[axw];
            uint2 ah1 = *(const uint2*)&Ahi[axw + 64];
            uint2 al0 = *(const uint2*)&Alo[axw];
            uint2 al1 = *(const uint2*)&Alo[axw + 64];
            #pragma unroll
            for (int ng = 0; ng < 4; ng++) {
                int bxw = sl * 512 + ng * 128 + qid * 8 + 2 * (c ^ (sl & 3));
                uint2 bh0 = *(const uint2*)&Bhi[bxw];
                uint2 bh1 = *(const uint2*)&Bhi[bxw + 64];
                uint2 bl0 = *(const uint2*)&Blo[bxw];
                uint2 bl1 = *(const uint2*)&Blo[bxw + 64];
                mma_bf16(acc[ng][0], ah0.x, ah1.x, ah0.y, ah1.y, bh0.x, bh0.y);
                mma_bf16(acc[ng][0], ah0.x, ah1.x, ah0.y, ah1.y, bl0.x, bl0.y);
                mma_bf16(acc[ng][0], al0.x, al1.x, al0.y, al1.y, bh0.x, bh0.y);
                mma_bf16(acc[ng][1], ah0.x, ah1.x, ah0.y, ah1.y, bh1.x, bh1.y);
                mma_bf16(acc[ng][1], ah0.x, ah1.x, ah0.y, ah1.y, bl1.x, bl1.y);
                mma_bf16(acc[ng][1], al0.x, al1.x, al0.y, al1.y, bh1.x, bh1.y);
            }
        }
    }

    const int mrow = m0 + w * 16 + qid;
    #pragma unroll
    for (int ng = 0; ng < 4; ng++) {
        #pragma unroll
        for (int hh = 0; hh < 2; hh++) {
            int col = n0 + ng * 16 + hh * 8 + 2 * c;
            float2 b2 = *(const float2*)(bias + col);
            float2 o0, o1;
            o0.x = acc[ng][hh][0] + b2.x; o0.y = acc[ng][hh][1] + b2.y;
            o1.x = acc[ng][hh][2] + b2.x; o1.y = acc[ng][hh][3] + b2.y;
            *(float2*)&E[(size_t)mrow * 1024 + col]       = o0;
            *(float2*)&E[(size_t)(mrow + 8) * 1024 + col] = o1;
        }
    }
}

// ---------------------------------------------------------------------------
// h0 -> bf16 transport buffer (read at t=0 as g_hbf[1])
// ---------------------------------------------------------------------------
__global__ void h0_to_bf16(const float* __restrict__ h0)
{
    int i = blockIdx.x * 256 + threadIdx.x;
    g_hbf[1][i] = __float2bfloat16(h0[i]);
}

// ---------------------------------------------------------------------------
// Per-m-group barrier: 16 CTAs, release/acquire atomics, monotonic counter.
// ---------------------------------------------------------------------------
__device__ __forceinline__ void group_barrier(int grp, unsigned target)
{
    __syncthreads();
    if (threadIdx.x == 0) {
        unsigned* ctr = &g_grp[grp][0];
        asm volatile("red.release.gpu.global.add.u32 [%0], %1;"
                     :: "l"(ctr), "r"(1u) : "memory");
        unsigned v;
        do {
            asm volatile("ld.acquire.gpu.global.u32 %0, [%1];"
                         : "=r"(v) : "l"(ctr) : "memory");
        } while (v < target);
    }
    __syncthreads();
}

// ---------------------------------------------------------------------------
// Persistent recurrence with bf16 tensor-core mma.
// R4 change: per step, bulk-load the WHOLE 32x1024 h tile (16 front-batched
// LDG.128/thread, MLP=16), stage into a single 64KB smem buffer, ONE
// __syncthreads, then all 64 mma slices run back-to-back with no memory deps.
// Removes 7 syncthreads + per-chunk L2-latency exposure from the step path.
// ---------------------------------------------------------------------------
__global__ void __launch_bounds__(256, 1)
rnn_persistent(const float* __restrict__ W_h,
               const float* __restrict__ b_h)
{
    extern __shared__ unsigned smw[];
    unsigned* Ws = smw;              // 32768 words (128KB)
    unsigned* As = smw + 32768;      // 16384 words (64KB) — full h tile

    const int tid  = threadIdx.x;
    const int lane = tid & 31;
    const int w    = tid >> 5;
    const int qid  = lane >> 2;
    const int c    = lane & 3;
    const int mw   = (w >> 2) * 16;
    const int nw   = (w & 3) * 16;
    const int cta  = blockIdx.x;
    const int grp  = cta >> 4;
    const int m0   = grp * MT;
    const int n0   = (cta & 15) * NT;

    // ---- fill Ws (once): fp32 -> bf16x2, fragment-shuffled ----
    for (int i = tid; i < NT * 512; i += 256) {
        int n  = i >> 9;
        int kp = i & 511;
        int k  = kp * 2;
        int s  = k >> 4;
        int p  = (k & 15) >> 1;
        float2 wv = *(const float2*)(W_h + (size_t)(n0 + n) * HID + k);
        __nv_bfloat162 bb = __float22bfloat162_rn(wv);
        Ws[s * 512 + n * 8 + (p & 3) * 2 + (p >> 2)] = *(unsigned*)&bb;
    }
    const float2 bh0 = *(const float2*)(b_h + n0 + nw + 2 * c);
    const float2 bh1 = *(const float2*)(b_h + n0 + nw + 8 + 2 * c);
    __syncthreads();

    const int srow = tid >> 3;
    const int ssl  = tid & 7;
    const int sx   = ssl & 3;

    for (int t = 0; t < T_STEPS; t++) {
        const __nv_bfloat16* hin  = g_hbf[(t + 1) & 1];
        __nv_bfloat16*       hout = g_hbf[t & 1];

        // ---- bulk load: whole h tile, 16 int4 per thread, front-batched ----
        const __nv_bfloat16* gsrc = hin + (size_t)(m0 + srow) * HID + ssl * 16;
        int4 v[16];
        #pragma unroll
        for (int ch = 0; ch < 8; ch++) {
            v[2 * ch]     = __ldcg((const int4*)(gsrc + ch * 128));
            v[2 * ch + 1] = __ldcg((const int4*)(gsrc + ch * 128 + 8));
        }

        // epilogue operands (overlap with h loads)
        const float* eb = g_E + ((size_t)t * BATCH + m0 + mw + qid) * HID
                              + n0 + nw + 2 * c;
        float2 e00 = __ldg((const float2*)eb);
        float2 e01 = __ldg((const float2*)(eb + 8));
        float2 e10 = __ldg((const float2*)(eb + 8 * HID));
        float2 e11 = __ldg((const float2*)(eb + 8 * HID + 8));

        // ---- stage all 8 chunks, one sync ----
        #pragma unroll
        for (int ch = 0; ch < 8; ch++) {
            uint2* dp = (uint2*)(As + ch * 2048 + ssl * 256 + srow * 8);
            int4 a = v[2 * ch], b = v[2 * ch + 1];
            dp[0 ^ sx] = make_uint2(a.x, b.x);
            dp[1 ^ sx] = make_uint2(a.y, b.y);
            dp[2 ^ sx] = make_uint2(a.z, b.z);
            dp[3 ^ sx] = make_uint2(a.w, b.w);
        }
        __syncthreads();

        float d0[4] = {0.f, 0.f, 0.f, 0.f};
        float d1[4] = {0.f, 0.f, 0.f, 0.f};

        // ---- compute: 64 slices, no memory dependencies ----
        #pragma unroll
        for (int ch = 0; ch < 8; ch++) {
            const unsigned* Ab = As + ch * 2048;
            #pragma unroll
            for (int sl = 0; sl < 8; sl++) {
                int aoff = sl * 256 + (mw + qid) * 8 + 2 * (c ^ (sl & 3));
                uint2 aLo = *(const uint2*)(Ab + aoff);
                uint2 aHi = *(const uint2*)(Ab + aoff + 64);
                const unsigned* Wb = Ws + (ch * 8 + sl) * 512 + (nw + qid) * 8 + 2 * c;
                uint2 b0 = *(const uint2*)(Wb);
                uint2 b1 = *(const uint2*)(Wb + 64);
                mma_bf16(d0, aLo.x, aHi.x, aLo.y, aHi.y, b0.x, b0.y);
                mma_bf16(d1, aLo.x, aHi.x, aLo.y, aHi.y, b1.x, b1.y);
            }
        }

        // ---- epilogue: z = d + b_h + E; h = sigmoid(z) (all fp32) ----
        float s00x = sigmoidf_fast(d0[0] + bh0.x + e00.x);
        float s00y = sigmoidf_fast(d0[1] + bh0.y + e00.y);
        float s10x = sigmoidf_fast(d0[2] + bh0.x + e10.x);
        float s10y = sigmoidf_fast(d0[3] + bh0.y + e10.y);
        float s01x = sigmoidf_fast(d1[0] + bh1.x + e01.x);
        float s01y = sigmoidf_fast(d1[1] + bh1.y + e01.y);
        float s11x = sigmoidf_fast(d1[2] + bh1.x + e11.x);
        float s11y = sigmoidf_fast(d1[3] + bh1.y + e11.y);

        __nv_bfloat16* ho = hout + (size_t)(m0 + mw + qid) * HID + n0 + nw + 2 * c;
        *(__nv_bfloat162*)(ho)               = __float22bfloat162_rn(make_float2(s00x, s00y));
        *(__nv_bfloat162*)(ho + 8)           = __float22bfloat162_rn(make_float2(s01x, s01y));
        *(__nv_bfloat162*)(ho + 8 * HID)     = __float22bfloat162_rn(make_float2(s10x, s10y));
        *(__nv_bfloat162*)(ho + 8 * HID + 8) = __float22bfloat162_rn(make_float2(s11x, s11y));

        if (t == T_STEPS - 1) {
            float* hf = g_hfinal + (size_t)(m0 + mw + qid) * HID + n0 + nw + 2 * c;
            *(float2*)(hf)               = make_float2(s00x, s00y);
            *(float2*)(hf + 8)           = make_float2(s01x, s01y);
            *(float2*)(hf + 8 * HID)     = make_float2(s10x, s10y);
            *(float2*)(hf + 8 * HID + 8) = make_float2(s11x, s11y);
        } else {
            group_barrier(grp, 16u * (t + 1));
        }
    }
}

// ---------------------------------------------------------------------------
// Final head (R4: all 128 threads participate in the dot product)
// ---------------------------------------------------------------------------
__global__ void finalize_kernel(const float* __restrict__ h,
                                const float* __restrict__ state_in,
                                const float* __restrict__ W_o,
                                const float* __restrict__ b_o,
                                float* __restrict__ out)
{
    const int b    = blockIdx.x;
    const int tid  = threadIdx.x;
    const int lane = tid & 31;
    const int wid  = tid >> 5;

    __shared__ float red[4][OUTD];
    __shared__ float logits[OUTD];

    float acc[OUTD];
    #pragma unroll
    for (int o = 0; o < OUTD; o++) acc[o] = 0.0f;
    for (int k = tid; k < HID; k += 128) {
        float hv = h[(size_t)b * HID + k];
        #pragma unroll
        for (int o = 0; o < OUTD; o++)
            acc[o] += hv * W_o[(size_t)o * HID + k];
    }
    #pragma unroll
    for (int o = 0; o < OUTD; o++) {
        float v = acc[o];
        #pragma unroll
        for (int s = 16; s > 0; s >>= 1)
            v += __shfl_xor_sync(0xffffffff, v, s);
        if (lane == 0) red[wid][o] = v;
    }
    __syncthreads();

    if (tid == 0) {
        #pragma unroll
        for (int o = 0; o < OUTD; o++)
            logits[o] = red[0][o] + red[1][o] + red[2][o] + red[3][o] + b_o[o];
        float m = logits[0];
        #pragma unroll
        for (int o = 1; o < OUTD; o++) m = fmaxf(m, logits[o]);
        float s = 0.0f;
        #pragma unroll
        for (int o = 0; o < OUTD; o++) s += expf(logits[o] - m);
        float lse = m + logf(s);
        #pragma unroll
        for (int o = 0; o < OUTD; o++)
            out[(size_t)b * OUTD + o] = logits[o] - lse;
    }

    float* hid_out = out + (size_t)BATCH * OUTD;
    float* st_out  = hid_out + (size_t)BATCH * HID;
    for (int k = tid; k < HID; k += blockDim.x) {
        hid_out[(size_t)b * HID + k] = h[(size_t)b * HID + k];
        st_out[(size_t)b * HID + k]  = state_in[(size_t)b * HID + k];
    }
}

extern "C" void kernel_launch(void* const* d_in, const int* in_sizes, int n_in,
                              void* d_out, int out_size)
{
    const float* x    = (const float*)d_in[0];
    const float* h0   = (const float*)d_in[1];
    const float* st   = (const float*)d_in[2];
    const float* W_in = (const float*)d_in[3];
    const float* b_in = (const float*)d_in[4];
    const float* W_h  = (const float*)d_in[5];
    const float* b_h  = (const float*)d_in[6];
    const float* W_o  = (const float*)d_in[7];
    const float* b_o  = (const float*)d_in[8];
    float* out = (float*)d_out;

    float* Eptr = nullptr;
    float* hfin = nullptr;
    unsigned* grpptr = nullptr;
    cudaGetSymbolAddress((void**)&Eptr, g_E);
    cudaGetSymbolAddress((void**)&hfin, g_hfinal);
    cudaGetSymbolAddress((void**)&grpptr, g_grp);

    cudaMemsetAsync(grpptr, 0, 8 * 32 * sizeof(unsigned));

    // 0) h0 -> bf16 transport buffer
    h0_to_bf16<<<(BATCH * HID) / 256, 256>>>(h0);

    // 1) E = x @ W_in^T + b_in (bf16 3-term split, fp32 accumulate)
    {
        const int smem_bytes = 24576 * sizeof(unsigned);  // 96KB
        cudaFuncSetAttribute(egemm_bf16x3,
                             cudaFuncAttributeMaxDynamicSharedMemorySize, smem_bytes);
        dim3 grid(HID / 64, (T_STEPS * BATCH) / 128);
        egemm_bf16x3<<<grid, 256, smem_bytes>>>(x, W_in, b_in, Eptr);
    }

    // 2) Persistent recurrence (bf16 tensor cores, bulk-load steps)
    {
        const int smem_bytes = (32768 + 16384) * sizeof(unsigned);  // 192KB
        cudaFuncSetAttribute(rnn_persistent,
                             cudaFuncAttributeMaxDynamicSharedMemorySize, smem_bytes);
        rnn_persistent<<<GRID_P, 256, smem_bytes>>>(W_h, b_h);
    }

    // 3) Head + output tuple
    finalize_kernel<<<BATCH, 128>>>(hfin, st, W_o, b_o, out);
}

// round 8
// speedup vs baseline: 1.2216x; 1.2210x over previous
#include <cuda_runtime.h>
#include <cuda_bf16.h>
#include <math.h>

// Problem dims (fixed by the reference)
#define T_STEPS 512
#define BATCH   256
#define DIM     1024
#define HID     1024
#define OUTD    5

// Persistent recurrence geometry: 128 CTAs = 8 m-tiles(32) x 16 n-tiles(64)
#define GRID_P  128
#define MT      32
#define NT      64

// Scratch
__device__ float          g_E[(size_t)T_STEPS * BATCH * HID];     // fp32 input proj
__device__ __nv_bfloat16  g_hbf[2][(size_t)BATCH * HID];          // bf16 h transport
__device__ float          g_hfinal[(size_t)BATCH * HID];          // fp32 final h
__device__ unsigned       g_grp[8][32];                           // per-m-group barrier ctrs

// ---------------------------------------------------------------------------
// bf16 mma.sync helper (m16n8k16, fp32 accumulate)
// ---------------------------------------------------------------------------
__device__ __forceinline__ void mma_bf16(float d[4],
                                         unsigned a0, unsigned a1,
                                         unsigned a2, unsigned a3,
                                         unsigned b0, unsigned b1)
{
    asm volatile(
        "mma.sync.aligned.m16n8k16.row.col.f32.bf16.bf16.f32 "
        "{%0,%1,%2,%3}, {%4,%5,%6,%7}, {%8,%9}, {%0,%1,%2,%3};"
        : "+f"(d[0]), "+f"(d[1]), "+f"(d[2]), "+f"(d[3])
        : "r"(a0), "r"(a1), "r"(a2), "r"(a3), "r"(b0), "r"(b1));
}

__device__ __forceinline__ float sigmoidf_fast(float x)
{
    return 1.0f / (1.0f + __expf(-x));
}

// ---------------------------------------------------------------------------
// E = x @ W_in^T + b_in, single-pass bf16 tensor-core GEMM (fp32 accumulate).
// R7: dropped the 3-term error-compensation split. Error model: ΔE ~ 1e-3 abs
// -> steady-state h error ~2e-4, inside budget. Halves chip-wide HMMA count.
// CTA tile 128m x 64n, K chunked by 128. 256 threads, 8 warps (warp = 16 m).
// Fragment layout identical to the validated R3-R6 scheme:
//   word(slice, row, p) = slice*256(or 512) + row*8 + (p&3)*2 + (p>>2),
//   uint2-index XOR swizzle by (slice&3) on both store and load.
// ---------------------------------------------------------------------------
__global__ void __launch_bounds__(256, 2)
egemm_bf16(const float* __restrict__ X,     // [131072, 1024]
           const float* __restrict__ Wg,    // [1024, 1024]
           const float* __restrict__ bias,  // [1024]
           float* __restrict__ E)
{
    extern __shared__ unsigned es[];
    unsigned* Ah = es;              // 4 groups x 2048 words = 8192 (32KB)
    unsigned* Bh = es + 8192;       // 8 slices x 512 words = 4096 (16KB)

    const int tid  = threadIdx.x;
    const int lane = tid & 31;
    const int w    = tid >> 5;
    const int qid  = lane >> 2;
    const int c    = lane & 3;
    const int g    = w >> 1;             // A row-group for this warp
    const int subm = (w & 1) * 16;       // row offset within group

    const int n0 = blockIdx.x * 64;
    const int m0 = blockIdx.y * 128;

    const int srow = tid >> 3;           // 0..31
    const int ssl  = tid & 7;            // slice 0..7
    const int sx   = ssl & 3;

    float acc[4][2][4];
    #pragma unroll
    for (int a = 0; a < 4; a++)
        #pragma unroll
        for (int b = 0; b < 2; b++)
            #pragma unroll
            for (int d = 0; d < 4; d++) acc[a][b][d] = 0.0f;

    for (int ch = 0; ch < 8; ch++) {
        __syncthreads();
        // ---- stage A: 128 rows x 128 k (4 row-slices per thread) ----
        const float* xbase = X + (size_t)(m0 + srow) * 1024 + ch * 128 + ssl * 16;
        #pragma unroll
        for (int jj = 0; jj < 4; jj++) {
            const float4* p = (const float4*)(xbase + (size_t)jj * 32 * 1024);
            float4 f0 = p[0], f1 = p[1], f2 = p[2], f3 = p[3];
            unsigned h[8];
            {
                __nv_bfloat162 b0 = __float22bfloat162_rn(make_float2(f0.x, f0.y));
                __nv_bfloat162 b1 = __float22bfloat162_rn(make_float2(f0.z, f0.w));
                __nv_bfloat162 b2 = __float22bfloat162_rn(make_float2(f1.x, f1.y));
                __nv_bfloat162 b3 = __float22bfloat162_rn(make_float2(f1.z, f1.w));
                __nv_bfloat162 b4 = __float22bfloat162_rn(make_float2(f2.x, f2.y));
                __nv_bfloat162 b5 = __float22bfloat162_rn(make_float2(f2.z, f2.w));
                __nv_bfloat162 b6 = __float22bfloat162_rn(make_float2(f3.x, f3.y));
                __nv_bfloat162 b7 = __float22bfloat162_rn(make_float2(f3.z, f3.w));
                h[0] = *(unsigned*)&b0; h[1] = *(unsigned*)&b1;
                h[2] = *(unsigned*)&b2; h[3] = *(unsigned*)&b3;
                h[4] = *(unsigned*)&b4; h[5] = *(unsigned*)&b5;
                h[6] = *(unsigned*)&b6; h[7] = *(unsigned*)&b7;
            }
            uint2* dh = (uint2*)&Ah[jj * 2048 + ssl * 256 + srow * 8];
            dh[0 ^ sx] = make_uint2(h[0], h[4]);
            dh[1 ^ sx] = make_uint2(h[1], h[5]);
            dh[2 ^ sx] = make_uint2(h[2], h[6]);
            dh[3 ^ sx] = make_uint2(h[3], h[7]);
        }
        // ---- stage B: 64 n-rows x 128 k (2 row-slices per thread) ----
        #pragma unroll
        for (int jj = 0; jj < 2; jj++) {
            int nrow = srow + jj * 32;
            const float4* p = (const float4*)(Wg + (size_t)(n0 + nrow) * 1024
                                              + ch * 128 + ssl * 16);
            float4 f0 = p[0], f1 = p[1], f2 = p[2], f3 = p[3];
            unsigned h[8];
            {
                __nv_bfloat162 b0 = __float22bfloat162_rn(make_float2(f0.x, f0.y));
                __nv_bfloat162 b1 = __float22bfloat162_rn(make_float2(f0.z, f0.w));
                __nv_bfloat162 b2 = __float22bfloat162_rn(make_float2(f1.x, f1.y));
                __nv_bfloat162 b3 = __float22bfloat162_rn(make_float2(f1.z, f1.w));
                __nv_bfloat162 b4 = __float22bfloat162_rn(make_float2(f2.x, f2.y));
                __nv_bfloat162 b5 = __float22bfloat162_rn(make_float2(f2.z, f2.w));
                __nv_bfloat162 b6 = __float22bfloat162_rn(make_float2(f3.x, f3.y));
                __nv_bfloat162 b7 = __float22bfloat162_rn(make_float2(f3.z, f3.w));
                h[0] = *(unsigned*)&b0; h[1] = *(unsigned*)&b1;
                h[2] = *(unsigned*)&b2; h[3] = *(unsigned*)&b3;
                h[4] = *(unsigned*)&b4; h[5] = *(unsigned*)&b5;
                h[6] = *(unsigned*)&b6; h[7] = *(unsigned*)&b7;
            }
            uint2* dh = (uint2*)&Bh[ssl * 512 + nrow * 8];
            dh[0 ^ sx] = make_uint2(h[0], h[4]);
            dh[1 ^ sx] = make_uint2(h[1], h[5]);
            dh[2 ^ sx] = make_uint2(h[2], h[6]);
            dh[3 ^ sx] = make_uint2(h[3], h[7]);
        }
        __syncthreads();

        // ---- mma: 8 slices x 4 n16-groups x 2 halves, single term ----
        #pragma unroll
        for (int sl = 0; sl < 8; sl++) {
            int axw = g * 2048 + sl * 256 + (subm + qid) * 8 + 2 * (c ^ (sl & 3));
            uint2 ah0 = *(const uint2*)&Ah[axw];
            uint2 ah1 = *(const uint2*)&Ah[axw + 64];
            #pragma unroll
            for (int ng = 0; ng < 4; ng++) {
                int bxw = sl * 512 + ng * 128 + qid * 8 + 2 * (c ^ (sl & 3));
                uint2 bh0 = *(const uint2*)&Bh[bxw];
                uint2 bh1 = *(const uint2*)&Bh[bxw + 64];
                mma_bf16(acc[ng][0], ah0.x, ah1.x, ah0.y, ah1.y, bh0.x, bh0.y);
                mma_bf16(acc[ng][1], ah0.x, ah1.x, ah0.y, ah1.y, bh1.x, bh1.y);
            }
        }
    }

    // ---- epilogue: add bias, store fp32 E ----
    const int mrow = m0 + w * 16 + qid;
    #pragma unroll
    for (int ng = 0; ng < 4; ng++) {
        #pragma unroll
        for (int hh = 0; hh < 2; hh++) {
            int col = n0 + ng * 16 + hh * 8 + 2 * c;
            float2 b2 = *(const float2*)(bias + col);
            float2 o0, o1;
            o0.x = acc[ng][hh][0] + b2.x; o0.y = acc[ng][hh][1] + b2.y;
            o1.x = acc[ng][hh][2] + b2.x; o1.y = acc[ng][hh][3] + b2.y;
            *(float2*)&E[(size_t)mrow * 1024 + col]       = o0;
            *(float2*)&E[(size_t)(mrow + 8) * 1024 + col] = o1;
        }
    }
}

// ---------------------------------------------------------------------------
// h0 -> bf16 transport buffer (read at t=0 as g_hbf[1])
// ---------------------------------------------------------------------------
__global__ void h0_to_bf16(const float* __restrict__ h0)
{
    int i = blockIdx.x * 256 + threadIdx.x;
    g_hbf[1][i] = __float2bfloat16(h0[i]);
}

// ---------------------------------------------------------------------------
// Per-m-group barrier: 16 CTAs, release/acquire atomics, monotonic counter.
// ---------------------------------------------------------------------------
__device__ __forceinline__ void group_barrier(int grp, unsigned target)
{
    __syncthreads();
    if (threadIdx.x == 0) {
        unsigned* ctr = &g_grp[grp][0];
        asm volatile("red.release.gpu.global.add.u32 [%0], %1;"
                     :: "l"(ctr), "r"(1u) : "memory");
        unsigned v;
        do {
            asm volatile("ld.acquire.gpu.global.u32 %0, [%1];"
                         : "=r"(v) : "l"(ctr) : "memory");
        } while (v < target);
    }
    __syncthreads();
}

// ---------------------------------------------------------------------------
// Persistent recurrence with bf16 tensor-core mma (byte-identical to the
// 6754us best: bulk-load whole 32x1024 h tile, one sync, 64 mma slices).
// ---------------------------------------------------------------------------
__global__ void __launch_bounds__(256, 1)
rnn_persistent(const float* __restrict__ W_h,
               const float* __restrict__ b_h)
{
    extern __shared__ unsigned smw[];
    unsigned* Ws = smw;              // 32768 words (128KB)
    unsigned* As = smw + 32768;      // 16384 words (64KB) — full h tile

    const int tid  = threadIdx.x;
    const int lane = tid & 31;
    const int w    = tid >> 5;
    const int qid  = lane >> 2;
    const int c    = lane & 3;
    const int mw   = (w >> 2) * 16;
    const int nw   = (w & 3) * 16;
    const int cta  = blockIdx.x;
    const int grp  = cta >> 4;
    const int m0   = grp * MT;
    const int n0   = (cta & 15) * NT;

    // ---- fill Ws (once): fp32 -> bf16x2, fragment-shuffled ----
    for (int i = tid; i < NT * 512; i += 256) {
        int n  = i >> 9;
        int kp = i & 511;
        int k  = kp * 2;
        int s  = k >> 4;
        int p  = (k & 15) >> 1;
        float2 wv = *(const float2*)(W_h + (size_t)(n0 + n) * HID + k);
        __nv_bfloat162 bb = __float22bfloat162_rn(wv);
        Ws[s * 512 + n * 8 + (p & 3) * 2 + (p >> 2)] = *(unsigned*)&bb;
    }
    const float2 bh0 = *(const float2*)(b_h + n0 + nw + 2 * c);
    const float2 bh1 = *(const float2*)(b_h + n0 + nw + 8 + 2 * c);
    __syncthreads();

    const int srow = tid >> 3;
    const int ssl  = tid & 7;
    const int sx   = ssl & 3;

    for (int t = 0; t < T_STEPS; t++) {
        const __nv_bfloat16* hin  = g_hbf[(t + 1) & 1];
        __nv_bfloat16*       hout = g_hbf[t & 1];

        // ---- bulk load: whole h tile, 16 int4 per thread, front-batched ----
        const __nv_bfloat16* gsrc = hin + (size_t)(m0 + srow) * HID + ssl * 16;
        int4 v[16];
        #pragma unroll
        for (int ch = 0; ch < 8; ch++) {
            v[2 * ch]     = __ldcg((const int4*)(gsrc + ch * 128));
            v[2 * ch + 1] = __ldcg((const int4*)(gsrc + ch * 128 + 8));
        }

        // epilogue operands (overlap with h loads)
        const float* eb = g_E + ((size_t)t * BATCH + m0 + mw + qid) * HID
                              + n0 + nw + 2 * c;
        float2 e00 = __ldg((const float2*)eb);
        float2 e01 = __ldg((const float2*)(eb + 8));
        float2 e10 = __ldg((const float2*)(eb + 8 * HID));
        float2 e11 = __ldg((const float2*)(eb + 8 * HID + 8));

        // ---- stage all 8 chunks, one sync ----
        #pragma unroll
        for (int ch = 0; ch < 8; ch++) {
            uint2* dp = (uint2*)(As + ch * 2048 + ssl * 256 + srow * 8);
            int4 a = v[2 * ch], b = v[2 * ch + 1];
            dp[0 ^ sx] = make_uint2(a.x, b.x);
            dp[1 ^ sx] = make_uint2(a.y, b.y);
            dp[2 ^ sx] = make_uint2(a.z, b.z);
            dp[3 ^ sx] = make_uint2(a.w, b.w);
        }
        __syncthreads();

        float d0[4] = {0.f, 0.f, 0.f, 0.f};
        float d1[4] = {0.f, 0.f, 0.f, 0.f};

        // ---- compute: 64 slices, no memory dependencies ----
        #pragma unroll
        for (int ch = 0; ch < 8; ch++) {
            const unsigned* Ab = As + ch * 2048;
            #pragma unroll
            for (int sl = 0; sl < 8; sl++) {
                int aoff = sl * 256 + (mw + qid) * 8 + 2 * (c ^ (sl & 3));
                uint2 aLo = *(const uint2*)(Ab + aoff);
                uint2 aHi = *(const uint2*)(Ab + aoff + 64);
                const unsigned* Wb = Ws + (ch * 8 + sl) * 512 + (nw + qid) * 8 + 2 * c;
                uint2 b0 = *(const uint2*)(Wb);
                uint2 b1 = *(const uint2*)(Wb + 64);
                mma_bf16(d0, aLo.x, aHi.x, aLo.y, aHi.y, b0.x, b0.y);
                mma_bf16(d1, aLo.x, aHi.x, aLo.y, aHi.y, b1.x, b1.y);
            }
        }

        // ---- epilogue: z = d + b_h + E; h = sigmoid(z) (all fp32) ----
        float s00x = sigmoidf_fast(d0[0] + bh0.x + e00.x);
        float s00y = sigmoidf_fast(d0[1] + bh0.y + e00.y);
        float s10x = sigmoidf_fast(d0[2] + bh0.x + e10.x);
        float s10y = sigmoidf_fast(d0[3] + bh0.y + e10.y);
        float s01x = sigmoidf_fast(d1[0] + bh1.x + e01.x);
        float s01y = sigmoidf_fast(d1[1] + bh1.y + e01.y);
        float s11x = sigmoidf_fast(d1[2] + bh1.x + e11.x);
        float s11y = sigmoidf_fast(d1[3] + bh1.y + e11.y);

        __nv_bfloat16* ho = hout + (size_t)(m0 + mw + qid) * HID + n0 + nw + 2 * c;
        *(__nv_bfloat162*)(ho)               = __float22bfloat162_rn(make_float2(s00x, s00y));
        *(__nv_bfloat162*)(ho + 8)           = __float22bfloat162_rn(make_float2(s01x, s01y));
        *(__nv_bfloat162*)(ho + 8 * HID)     = __float22bfloat162_rn(make_float2(s10x, s10y));
        *(__nv_bfloat162*)(ho + 8 * HID + 8) = __float22bfloat162_rn(make_float2(s11x, s11y));

        if (t == T_STEPS - 1) {
            float* hf = g_hfinal + (size_t)(m0 + mw + qid) * HID + n0 + nw + 2 * c;
            *(float2*)(hf)               = make_float2(s00x, s00y);
            *(float2*)(hf + 8)           = make_float2(s01x, s01y);
            *(float2*)(hf + 8 * HID)     = make_float2(s10x, s10y);
            *(float2*)(hf + 8 * HID + 8) = make_float2(s11x, s11y);
        } else {
            group_barrier(grp, 16u * (t + 1));
        }
    }
}

// ---------------------------------------------------------------------------
// Final head (all 128 threads participate in the dot product)
// ---------------------------------------------------------------------------
__global__ void finalize_kernel(const float* __restrict__ h,
                                const float* __restrict__ state_in,
                                const float* __restrict__ W_o,
                                const float* __restrict__ b_o,
                                float* __restrict__ out)
{
    const int b    = blockIdx.x;
    const int tid  = threadIdx.x;
    const int lane = tid & 31;
    const int wid  = tid >> 5;

    __shared__ float red[4][OUTD];
    __shared__ float logits[OUTD];

    float acc[OUTD];
    #pragma unroll
    for (int o = 0; o < OUTD; o++) acc[o] = 0.0f;
    for (int k = tid; k < HID; k += 128) {
        float hv = h[(size_t)b * HID + k];
        #pragma unroll
        for (int o = 0; o < OUTD; o++)
            acc[o] += hv * W_o[(size_t)o * HID + k];
    }
    #pragma unroll
    for (int o = 0; o < OUTD; o++) {
        float v = acc[o];
        #pragma unroll
        for (int s = 16; s > 0; s >>= 1)
            v += __shfl_xor_sync(0xffffffff, v, s);
        if (lane == 0) red[wid][o] = v;
    }
    __syncthreads();

    if (tid == 0) {
        #pragma unroll
        for (int o = 0; o < OUTD; o++)
            logits[o] = red[0][o] + red[1][o] + red[2][o] + red[3][o] + b_o[o];
        float m = logits[0];
        #pragma unroll
        for (int o = 1; o < OUTD; o++) m = fmaxf(m, logits[o]);
        float s = 0.0f;
        #pragma unroll
        for (int o = 0; o < OUTD; o++) s += expf(logits[o] - m);
        float lse = m + logf(s);
        #pragma unroll
        for (int o = 0; o < OUTD; o++)
            out[(size_t)b * OUTD + o] = logits[o] - lse;
    }

    float* hid_out = out + (size_t)BATCH * OUTD;
    float* st_out  = hid_out + (size_t)BATCH * HID;
    for (int k = tid; k < HID; k += blockDim.x) {
        hid_out[(size_t)b * HID + k] = h[(size_t)b * HID + k];
        st_out[(size_t)b * HID + k]  = state_in[(size_t)b * HID + k];
    }
}

extern "C" void kernel_launch(void* const* d_in, const int* in_sizes, int n_in,
                              void* d_out, int out_size)
{
    const float* x    = (const float*)d_in[0];
    const float* h0   = (const float*)d_in[1];
    const float* st   = (const float*)d_in[2];
    const float* W_in = (const float*)d_in[3];
    const float* b_in = (const float*)d_in[4];
    const float* W_h  = (const float*)d_in[5];
    const float* b_h  = (const float*)d_in[6];
    const float* W_o  = (const float*)d_in[7];
    const float* b_o  = (const float*)d_in[8];
    float* out = (float*)d_out;

    float* Eptr = nullptr;
    float* hfin = nullptr;
    unsigned* grpptr = nullptr;
    cudaGetSymbolAddress((void**)&Eptr, g_E);
    cudaGetSymbolAddress((void**)&hfin, g_hfinal);
    cudaGetSymbolAddress((void**)&grpptr, g_grp);

    cudaMemsetAsync(grpptr, 0, 8 * 32 * sizeof(unsigned));

    // 0) h0 -> bf16 transport buffer
    h0_to_bf16<<<(BATCH * HID) / 256, 256>>>(h0);

    // 1) E = x @ W_in^T + b_in (single-pass bf16, fp32 accumulate)
    {
        const int smem_bytes = 12288 * sizeof(unsigned);  // 48KB
        cudaFuncSetAttribute(egemm_bf16,
                             cudaFuncAttributeMaxDynamicSharedMemorySize, smem_bytes);
        dim3 grid(HID / 64, (T_STEPS * BATCH) / 128);
        egemm_bf16<<<grid, 256, smem_bytes>>>(x, W_in, b_in, Eptr);
    }

    // 2) Persistent recurrence (unchanged 6754us-best kernel)
    {
        const int smem_bytes = (32768 + 16384) * sizeof(unsigned);  // 192KB
        cudaFuncSetAttribute(rnn_persistent,
                             cudaFuncAttributeMaxDynamicSharedMemorySize, smem_bytes);
        rnn_persistent<<<GRID_P, 256, smem_bytes>>>(W_h, b_h);
    }

    // 3) Head + output tuple
    finalize_kernel<<<BATCH, 128>>>(hfin, st, W_o, b_o, out);
}

// round 9
// speedup vs baseline: 1.2794x; 1.0473x over previous
#include <cuda_runtime.h>
#include <cuda_bf16.h>
#include <math.h>

// Problem dims (fixed by the reference)
#define T_STEPS 512
#define BATCH   256
#define DIM     1024
#define HID     1024
#define OUTD    5

// Persistent recurrence geometry: 128 CTAs = 8 m-tiles(32) x 16 n-tiles(64)
#define GRID_P  128
#define MT      32
#define NT      64

// Scratch
__device__ float          g_E[(size_t)T_STEPS * BATCH * HID];     // fp32 input proj
__device__ __nv_bfloat16  g_hbf[2][(size_t)BATCH * HID];          // bf16 h transport
__device__ float          g_hfinal[(size_t)BATCH * HID];          // fp32 final h
__device__ unsigned       g_grp[8][32];                           // per-m-group barrier ctrs

// ---------------------------------------------------------------------------
// bf16 mma.sync helper (m16n8k16, fp32 accumulate)
// ---------------------------------------------------------------------------
__device__ __forceinline__ void mma_bf16(float d[4],
                                         unsigned a0, unsigned a1,
                                         unsigned a2, unsigned a3,
                                         unsigned b0, unsigned b1)
{
    asm volatile(
        "mma.sync.aligned.m16n8k16.row.col.f32.bf16.bf16.f32 "
        "{%0,%1,%2,%3}, {%4,%5,%6,%7}, {%8,%9}, {%0,%1,%2,%3};"
        : "+f"(d[0]), "+f"(d[1]), "+f"(d[2]), "+f"(d[3])
        : "r"(a0), "r"(a1), "r"(a2), "r"(a3), "r"(b0), "r"(b1));
}

__device__ __forceinline__ float sigmoidf_fast(float x)
{
    return 1.0f / (1.0f + __expf(-x));
}

// ---------------------------------------------------------------------------
// E = x @ W_in^T + b_in, single-pass bf16 tensor-core GEMM (validated R7).
// ---------------------------------------------------------------------------
__global__ void __launch_bounds__(256, 2)
egemm_bf16(const float* __restrict__ X,     // [131072, 1024]
           const float* __restrict__ Wg,    // [1024, 1024]
           const float* __restrict__ bias,  // [1024]
           float* __restrict__ E)
{
    extern __shared__ unsigned es[];
    unsigned* Ah = es;              // 8192 words (32KB)
    unsigned* Bh = es + 8192;       // 4096 words (16KB)

    const int tid  = threadIdx.x;
    const int lane = tid & 31;
    const int w    = tid >> 5;
    const int qid  = lane >> 2;
    const int c    = lane & 3;
    const int g    = w >> 1;
    const int subm = (w & 1) * 16;

    const int n0 = blockIdx.x * 64;
    const int m0 = blockIdx.y * 128;

    const int srow = tid >> 3;
    const int ssl  = tid & 7;
    const int sx   = ssl & 3;

    float acc[4][2][4];
    #pragma unroll
    for (int a = 0; a < 4; a++)
        #pragma unroll
        for (int b = 0; b < 2; b++)
            #pragma unroll
            for (int d = 0; d < 4; d++) acc[a][b][d] = 0.0f;

    for (int ch = 0; ch < 8; ch++) {
        __syncthreads();
        const float* xbase = X + (size_t)(m0 + srow) * 1024 + ch * 128 + ssl * 16;
        #pragma unroll
        for (int jj = 0; jj < 4; jj++) {
            const float4* p = (const float4*)(xbase + (size_t)jj * 32 * 1024);
            float4 f0 = p[0], f1 = p[1], f2 = p[2], f3 = p[3];
            unsigned h[8];
            {
                __nv_bfloat162 b0 = __float22bfloat162_rn(make_float2(f0.x, f0.y));
                __nv_bfloat162 b1 = __float22bfloat162_rn(make_float2(f0.z, f0.w));
                __nv_bfloat162 b2 = __float22bfloat162_rn(make_float2(f1.x, f1.y));
                __nv_bfloat162 b3 = __float22bfloat162_rn(make_float2(f1.z, f1.w));
                __nv_bfloat162 b4 = __float22bfloat162_rn(make_float2(f2.x, f2.y));
                __nv_bfloat162 b5 = __float22bfloat162_rn(make_float2(f2.z, f2.w));
                __nv_bfloat162 b6 = __float22bfloat162_rn(make_float2(f3.x, f3.y));
                __nv_bfloat162 b7 = __float22bfloat162_rn(make_float2(f3.z, f3.w));
                h[0] = *(unsigned*)&b0; h[1] = *(unsigned*)&b1;
                h[2] = *(unsigned*)&b2; h[3] = *(unsigned*)&b3;
                h[4] = *(unsigned*)&b4; h[5] = *(unsigned*)&b5;
                h[6] = *(unsigned*)&b6; h[7] = *(unsigned*)&b7;
            }
            uint2* dh = (uint2*)&Ah[jj * 2048 + ssl * 256 + srow * 8];
            dh[0 ^ sx] = make_uint2(h[0], h[4]);
            dh[1 ^ sx] = make_uint2(h[1], h[5]);
            dh[2 ^ sx] = make_uint2(h[2], h[6]);
            dh[3 ^ sx] = make_uint2(h[3], h[7]);
        }
        #pragma unroll
        for (int jj = 0; jj < 2; jj++) {
            int nrow = srow + jj * 32;
            const float4* p = (const float4*)(Wg + (size_t)(n0 + nrow) * 1024
                                              + ch * 128 + ssl * 16);
            float4 f0 = p[0], f1 = p[1], f2 = p[2], f3 = p[3];
            unsigned h[8];
            {
                __nv_bfloat162 b0 = __float22bfloat162_rn(make_float2(f0.x, f0.y));
                __nv_bfloat162 b1 = __float22bfloat162_rn(make_float2(f0.z, f0.w));
                __nv_bfloat162 b2 = __float22bfloat162_rn(make_float2(f1.x, f1.y));
                __nv_bfloat162 b3 = __float22bfloat162_rn(make_float2(f1.z, f1.w));
                __nv_bfloat162 b4 = __float22bfloat162_rn(make_float2(f2.x, f2.y));
                __nv_bfloat162 b5 = __float22bfloat162_rn(make_float2(f2.z, f2.w));
                __nv_bfloat162 b6 = __float22bfloat162_rn(make_float2(f3.x, f3.y));
                __nv_bfloat162 b7 = __float22bfloat162_rn(make_float2(f3.z, f3.w));
                h[0] = *(unsigned*)&b0; h[1] = *(unsigned*)&b1;
                h[2] = *(unsigned*)&b2; h[3] = *(unsigned*)&b3;
                h[4] = *(unsigned*)&b4; h[5] = *(unsigned*)&b5;
                h[6] = *(unsigned*)&b6; h[7] = *(unsigned*)&b7;
            }
            uint2* dh = (uint2*)&Bh[ssl * 512 + nrow * 8];
            dh[0 ^ sx] = make_uint2(h[0], h[4]);
            dh[1 ^ sx] = make_uint2(h[1], h[5]);
            dh[2 ^ sx] = make_uint2(h[2], h[6]);
            dh[3 ^ sx] = make_uint2(h[3], h[7]);
        }
        __syncthreads();

        #pragma unroll
        for (int sl = 0; sl < 8; sl++) {
            int axw = g * 2048 + sl * 256 + (subm + qid) * 8 + 2 * (c ^ (sl & 3));
            uint2 ah0 = *(const uint2*)&Ah[axw];
            uint2 ah1 = *(const uint2*)&Ah[axw + 64];
            #pragma unroll
            for (int ng = 0; ng < 4; ng++) {
                int bxw = sl * 512 + ng * 128 + qid * 8 + 2 * (c ^ (sl & 3));
                uint2 bh0 = *(const uint2*)&Bh[bxw];
                uint2 bh1 = *(const uint2*)&Bh[bxw + 64];
                mma_bf16(acc[ng][0], ah0.x, ah1.x, ah0.y, ah1.y, bh0.x, bh0.y);
                mma_bf16(acc[ng][1], ah0.x, ah1.x, ah0.y, ah1.y, bh1.x, bh1.y);
            }
        }
    }

    const int mrow = m0 + w * 16 + qid;
    #pragma unroll
    for (int ng = 0; ng < 4; ng++) {
        #pragma unroll
        for (int hh = 0; hh < 2; hh++) {
            int col = n0 + ng * 16 + hh * 8 + 2 * c;
            float2 b2 = *(const float2*)(bias + col);
            float2 o0, o1;
            o0.x = acc[ng][hh][0] + b2.x; o0.y = acc[ng][hh][1] + b2.y;
            o1.x = acc[ng][hh][2] + b2.x; o1.y = acc[ng][hh][3] + b2.y;
            *(float2*)&E[(size_t)mrow * 1024 + col]       = o0;
            *(float2*)&E[(size_t)(mrow + 8) * 1024 + col] = o1;
        }
    }
}

// ---------------------------------------------------------------------------
__global__ void h0_to_bf16(const float* __restrict__ h0)
{
    int i = blockIdx.x * 256 + threadIdx.x;
    g_hbf[1][i] = __float2bfloat16(h0[i]);
}

// ---------------------------------------------------------------------------
// Per-m-group barrier: 16 CTAs, release/acquire atomics, monotonic counter.
// ---------------------------------------------------------------------------
__device__ __forceinline__ void group_barrier(int grp, unsigned target)
{
    __syncthreads();
    if (threadIdx.x == 0) {
        unsigned* ctr = &g_grp[grp][0];
        asm volatile("red.release.gpu.global.add.u32 [%0], %1;"
                     :: "l"(ctr), "r"(1u) : "memory");
        unsigned v;
        do {
            asm volatile("ld.acquire.gpu.global.u32 %0, [%1];"
                         : "=r"(v) : "l"(ctr) : "memory");
        } while (v < target);
    }
    __syncthreads();
}

// ---------------------------------------------------------------------------
// Persistent recurrence with bf16 tensor-core mma.
// R8 change: 8 independent accumulator chains per warp (d0[4], d1[4],
// chain = sl&3) so dependent HMMAs recur every 8 instructions instead of
// every 2 — removes the exposed RAW-latency of the 64-deep accumulator
// chains that (per the R4-NEUTRAL evidence) dominated the step time.
// Everything else byte-identical to the 5554us kernel.
// ---------------------------------------------------------------------------
__global__ void __launch_bounds__(256, 1)
rnn_persistent(const float* __restrict__ W_h,
               const float* __restrict__ b_h)
{
    extern __shared__ unsigned smw[];
    unsigned* Ws = smw;              // 32768 words (128KB)
    unsigned* As = smw + 32768;      // 16384 words (64KB) — full h tile

    const int tid  = threadIdx.x;
    const int lane = tid & 31;
    const int w    = tid >> 5;
    const int qid  = lane >> 2;
    const int c    = lane & 3;
    const int mw   = (w >> 2) * 16;
    const int nw   = (w & 3) * 16;
    const int cta  = blockIdx.x;
    const int grp  = cta >> 4;
    const int m0   = grp * MT;
    const int n0   = (cta & 15) * NT;

    // ---- fill Ws (once): fp32 -> bf16x2, fragment-shuffled ----
    for (int i = tid; i < NT * 512; i += 256) {
        int n  = i >> 9;
        int kp = i & 511;
        int k  = kp * 2;
        int s  = k >> 4;
        int p  = (k & 15) >> 1;
        float2 wv = *(const float2*)(W_h + (size_t)(n0 + n) * HID + k);
        __nv_bfloat162 bb = __float22bfloat162_rn(wv);
        Ws[s * 512 + n * 8 + (p & 3) * 2 + (p >> 2)] = *(unsigned*)&bb;
    }
    const float2 bh0 = *(const float2*)(b_h + n0 + nw + 2 * c);
    const float2 bh1 = *(const float2*)(b_h + n0 + nw + 8 + 2 * c);
    __syncthreads();

    const int srow = tid >> 3;
    const int ssl  = tid & 7;
    const int sx   = ssl & 3;

    for (int t = 0; t < T_STEPS; t++) {
        const __nv_bfloat16* hin  = g_hbf[(t + 1) & 1];
        __nv_bfloat16*       hout = g_hbf[t & 1];

        // ---- bulk load: whole h tile, 16 int4 per thread, front-batched ----
        const __nv_bfloat16* gsrc = hin + (size_t)(m0 + srow) * HID + ssl * 16;
        int4 v[16];
        #pragma unroll
        for (int ch = 0; ch < 8; ch++) {
            v[2 * ch]     = __ldcg((const int4*)(gsrc + ch * 128));
            v[2 * ch + 1] = __ldcg((const int4*)(gsrc + ch * 128 + 8));
        }

        // epilogue operands (overlap with h loads)
        const float* eb = g_E + ((size_t)t * BATCH + m0 + mw + qid) * HID
                              + n0 + nw + 2 * c;
        float2 e00 = __ldg((const float2*)eb);
        float2 e01 = __ldg((const float2*)(eb + 8));
        float2 e10 = __ldg((const float2*)(eb + 8 * HID));
        float2 e11 = __ldg((const float2*)(eb + 8 * HID + 8));

        // ---- stage all 8 chunks, one sync ----
        #pragma unroll
        for (int ch = 0; ch < 8; ch++) {
            uint2* dp = (uint2*)(As + ch * 2048 + ssl * 256 + srow * 8);
            int4 a = v[2 * ch], b = v[2 * ch + 1];
            dp[0 ^ sx] = make_uint2(a.x, b.x);
            dp[1 ^ sx] = make_uint2(a.y, b.y);
            dp[2 ^ sx] = make_uint2(a.z, b.z);
            dp[3 ^ sx] = make_uint2(a.w, b.w);
        }
        __syncthreads();

        // ---- compute: 64 slices, 8 independent accumulator chains ----
        float d0[4][4];
        float d1[4][4];
        #pragma unroll
        for (int cc = 0; cc < 4; cc++)
            #pragma unroll
            for (int j = 0; j < 4; j++) { d0[cc][j] = 0.f; d1[cc][j] = 0.f; }

        #pragma unroll
        for (int ch = 0; ch < 8; ch++) {
            const unsigned* Ab = As + ch * 2048;
            #pragma unroll
            for (int sl = 0; sl < 8; sl++) {
                const int cc = sl & 3;
                int aoff = sl * 256 + (mw + qid) * 8 + 2 * (c ^ (sl & 3));
                uint2 aLo = *(const uint2*)(Ab + aoff);
                uint2 aHi = *(const uint2*)(Ab + aoff + 64);
                const unsigned* Wb = Ws + (ch * 8 + sl) * 512 + (nw + qid) * 8 + 2 * c;
                uint2 b0 = *(const uint2*)(Wb);
                uint2 b1 = *(const uint2*)(Wb + 64);
                mma_bf16(d0[cc], aLo.x, aHi.x, aLo.y, aHi.y, b0.x, b0.y);
                mma_bf16(d1[cc], aLo.x, aHi.x, aLo.y, aHi.y, b1.x, b1.y);
            }
        }

        // pairwise reduction of the 4 chains per n8-half
        float f0[4], f1[4];
        #pragma unroll
        for (int j = 0; j < 4; j++) {
            f0[j] = (d0[0][j] + d0[1][j]) + (d0[2][j] + d0[3][j]);
            f1[j] = (d1[0][j] + d1[1][j]) + (d1[2][j] + d1[3][j]);
        }

        // ---- epilogue: z = f + b_h + E; h = sigmoid(z) (all fp32) ----
        float s00x = sigmoidf_fast(f0[0] + bh0.x + e00.x);
        float s00y = sigmoidf_fast(f0[1] + bh0.y + e00.y);
        float s10x = sigmoidf_fast(f0[2] + bh0.x + e10.x);
        float s10y = sigmoidf_fast(f0[3] + bh0.y + e10.y);
        float s01x = sigmoidf_fast(f1[0] + bh1.x + e01.x);
        float s01y = sigmoidf_fast(f1[1] + bh1.y + e01.y);
        float s11x = sigmoidf_fast(f1[2] + bh1.x + e11.x);
        float s11y = sigmoidf_fast(f1[3] + bh1.y + e11.y);

        __nv_bfloat16* ho = hout + (size_t)(m0 + mw + qid) * HID + n0 + nw + 2 * c;
        *(__nv_bfloat162*)(ho)               = __float22bfloat162_rn(make_float2(s00x, s00y));
        *(__nv_bfloat162*)(ho + 8)           = __float22bfloat162_rn(make_float2(s01x, s01y));
        *(__nv_bfloat162*)(ho + 8 * HID)     = __float22bfloat162_rn(make_float2(s10x, s10y));
        *(__nv_bfloat162*)(ho + 8 * HID + 8) = __float22bfloat162_rn(make_float2(s11x, s11y));

        if (t == T_STEPS - 1) {
            float* hf = g_hfinal + (size_t)(m0 + mw + qid) * HID + n0 + nw + 2 * c;
            *(float2*)(hf)               = make_float2(s00x, s00y);
            *(float2*)(hf + 8)           = make_float2(s01x, s01y);
            *(float2*)(hf + 8 * HID)     = make_float2(s10x, s10y);
            *(float2*)(hf + 8 * HID + 8) = make_float2(s11x, s11y);
        } else {
            group_barrier(grp, 16u * (t + 1));
        }
    }
}

// ---------------------------------------------------------------------------
// Final head (all 128 threads participate in the dot product)
// ---------------------------------------------------------------------------
__global__ void finalize_kernel(const float* __restrict__ h,
                                const float* __restrict__ state_in,
                                const float* __restrict__ W_o,
                                const float* __restrict__ b_o,
                                float* __restrict__ out)
{
    const int b    = blockIdx.x;
    const int tid  = threadIdx.x;
    const int lane = tid & 31;
    const int wid  = tid >> 5;

    __shared__ float red[4][OUTD];
    __shared__ float logits[OUTD];

    float acc[OUTD];
    #pragma unroll
    for (int o = 0; o < OUTD; o++) acc[o] = 0.0f;
    for (int k = tid; k < HID; k += 128) {
        float hv = h[(size_t)b * HID + k];
        #pragma unroll
        for (int o = 0; o < OUTD; o++)
            acc[o] += hv * W_o[(size_t)o * HID + k];
    }
    #pragma unroll
    for (int o = 0; o < OUTD; o++) {
        float v = acc[o];
        #pragma unroll
        for (int s = 16; s > 0; s >>= 1)
            v += __shfl_xor_sync(0xffffffff, v, s);
        if (lane == 0) red[wid][o] = v;
    }
    __syncthreads();

    if (tid == 0) {
        #pragma unroll
        for (int o = 0; o < OUTD; o++)
            logits[o] = red[0][o] + red[1][o] + red[2][o] + red[3][o] + b_o[o];
        float m = logits[0];
        #pragma unroll
        for (int o = 1; o < OUTD; o++) m = fmaxf(m, logits[o]);
        float s = 0.0f;
        #pragma unroll
        for (int o = 0; o < OUTD; o++) s += expf(logits[o] - m);
        float lse = m + logf(s);
        #pragma unroll
        for (int o = 0; o < OUTD; o++)
            out[(size_t)b * OUTD + o] = logits[o] - lse;
    }

    float* hid_out = out + (size_t)BATCH * OUTD;
    float* st_out  = hid_out + (size_t)BATCH * HID;
    for (int k = tid; k < HID; k += blockDim.x) {
        hid_out[(size_t)b * HID + k] = h[(size_t)b * HID + k];
        st_out[(size_t)b * HID + k]  = state_in[(size_t)b * HID + k];
    }
}

extern "C" void kernel_launch(void* const* d_in, const int* in_sizes, int n_in,
                              void* d_out, int out_size)
{
    const float* x    = (const float*)d_in[0];
    const float* h0   = (const float*)d_in[1];
    const float* st   = (const float*)d_in[2];
    const float* W_in = (const float*)d_in[3];
    const float* b_in = (const float*)d_in[4];
    const float* W_h  = (const float*)d_in[5];
    const float* b_h  = (const float*)d_in[6];
    const float* W_o  = (const float*)d_in[7];
    const float* b_o  = (const float*)d_in[8];
    float* out = (float*)d_out;

    float* Eptr = nullptr;
    float* hfin = nullptr;
    unsigned* grpptr = nullptr;
    cudaGetSymbolAddress((void**)&Eptr, g_E);
    cudaGetSymbolAddress((void**)&hfin, g_hfinal);
    cudaGetSymbolAddress((void**)&grpptr, g_grp);

    cudaMemsetAsync(grpptr, 0, 8 * 32 * sizeof(unsigned));

    // 0) h0 -> bf16 transport buffer
    h0_to_bf16<<<(BATCH * HID) / 256, 256>>>(h0);

    // 1) E = x @ W_in^T + b_in (single-pass bf16, fp32 accumulate)
    {
        const int smem_bytes = 12288 * sizeof(unsigned);  // 48KB
        cudaFuncSetAttribute(egemm_bf16,
                             cudaFuncAttributeMaxDynamicSharedMemorySize, smem_bytes);
        dim3 grid(HID / 64, (T_STEPS * BATCH) / 128);
        egemm_bf16<<<grid, 256, smem_bytes>>>(x, W_in, b_in, Eptr);
    }

    // 2) Persistent recurrence (R8: 8 accumulator chains per warp)
    {
        const int smem_bytes = (32768 + 16384) * sizeof(unsigned);  // 192KB
        cudaFuncSetAttribute(rnn_persistent,
                             cudaFuncAttributeMaxDynamicSharedMemorySize, smem_bytes);
        rnn_persistent<<<GRID_P, 256, smem_bytes>>>(W_h, b_h);
    }

    // 3) Head + output tuple
    finalize_kernel<<<BATCH, 128>>>(hfin, st, W_o, b_o, out);
}